// round 1
// baseline (speedup 1.0000x reference)
#include <cuda_runtime.h>

// out[k] = sum_{n=0..99} sum_{d=0..3} x[d] * M[n][d][k]
// Flatten M as 400 rows of float4 (row p = (n,d), components = k).
// out = sum_p x[p%4] * Mrow[p]   (a 4-vector accumulation)
//
// Single warp: thread t handles rows p = t, t+32, t+64, ... (<400).
// Since 32 ≡ 0 (mod 4), p%4 == t%4 for all rows of a given thread, so the
// x-scalar is loop-invariant. Each iteration: one coalesced LDG.128 + 4 FFMA.
// Butterfly shfl reduction, lane 0 writes the float4 result.

__global__ void __launch_bounds__(32, 1)
bigfanout_kernel(const float* __restrict__ x,
                 const float* __restrict__ matrices,
                 float* __restrict__ out) {
    const int t = threadIdx.x;            // 0..31
    const float xv = x[t & 3];            // loop-invariant per thread

    const float4* __restrict__ rows = reinterpret_cast<const float4*>(matrices);

    float a0 = 0.f, a1 = 0.f, a2 = 0.f, a3 = 0.f;

    // 400 rows total: threads 0..15 do 13 rows, threads 16..31 do 12.
    #pragma unroll
    for (int j = 0; j < 13; ++j) {
        int p = t + 32 * j;
        if (p < 400) {
            float4 r = rows[p];
            a0 = fmaf(xv, r.x, a0);
            a1 = fmaf(xv, r.y, a1);
            a2 = fmaf(xv, r.z, a2);
            a3 = fmaf(xv, r.w, a3);
        }
    }

    // Warp butterfly reduce each component across all 32 lanes.
    #pragma unroll
    for (int m = 16; m > 0; m >>= 1) {
        a0 += __shfl_xor_sync(0xFFFFFFFFu, a0, m);
        a1 += __shfl_xor_sync(0xFFFFFFFFu, a1, m);
        a2 += __shfl_xor_sync(0xFFFFFFFFu, a2, m);
        a3 += __shfl_xor_sync(0xFFFFFFFFu, a3, m);
    }

    if (t == 0) {
        float4 o = make_float4(a0, a1, a2, a3);
        *reinterpret_cast<float4*>(out) = o;
    }
}

extern "C" void kernel_launch(void* const* d_in, const int* in_sizes, int n_in,
                              void* d_out, int out_size) {
    const float* x        = (const float*)d_in[0];   // [1,4] float32
    const float* matrices = (const float*)d_in[1];   // [100,4,4] float32
    float* out            = (float*)d_out;           // [4] float32

    bigfanout_kernel<<<1, 32>>>(x, matrices, out);
}

// round 2
// speedup vs baseline: 1.4931x; 1.4931x over previous
#include <cuda_runtime.h>

// out[k] = sum_{n,d} x[d] * M[n][d][k],  M flattened to 400 float4 rows.
// Single warp. Lane t owns rows p = t + 32*j. Since 32 % 4 == 0, the x scalar
// x[p & 3] == x[t & 3] is loop-invariant per lane.
//
// 400 = 32*12 + 16: 12 unconditional float4 loads + 1 predicated tail (t<16).
// Dual accumulators halve the FFMA dependency chain.
// Component-folding butterfly: 6 SHFLs total (vs 20), depth 5.
//   stage xor 1: fold 4 comps -> 2   (2 shfls)
//   stage xor 2: fold 2 comps -> 1   (1 shfl)
//   stages xor 4,8,16: scalar sum    (3 shfls)
// Lane t<4 then holds out[k] with k = 2*(t&1) + ((t>>1)&1); scalar store.

__global__ void __launch_bounds__(32, 1)
bigfanout_kernel(const float* __restrict__ x,
                 const float* __restrict__ matrices,
                 float* __restrict__ out) {
    const int t = threadIdx.x;            // 0..31
    const float xv = x[t & 3];            // loop-invariant per lane

    const float4* __restrict__ rows = reinterpret_cast<const float4*>(matrices);

    // Dual accumulators (even/odd iteration) to shorten the FFMA chain.
    float e0 = 0.f, e1 = 0.f, e2 = 0.f, e3 = 0.f;
    float o0 = 0.f, o1 = 0.f, o2 = 0.f, o3 = 0.f;

    #pragma unroll
    for (int j = 0; j < 12; j += 2) {
        float4 re = rows[t + 32 * j];
        float4 ro = rows[t + 32 * (j + 1)];
        e0 = fmaf(xv, re.x, e0);  e1 = fmaf(xv, re.y, e1);
        e2 = fmaf(xv, re.z, e2);  e3 = fmaf(xv, re.w, e3);
        o0 = fmaf(xv, ro.x, o0);  o1 = fmaf(xv, ro.y, o1);
        o2 = fmaf(xv, ro.z, o2);  o3 = fmaf(xv, ro.w, o3);
    }

    // Tail: rows 384..399, lanes 0..15 only. 384 % 4 == 0 so xv still valid.
    if (t < 16) {
        float4 r = rows[384 + t];
        e0 = fmaf(xv, r.x, e0);  e1 = fmaf(xv, r.y, e1);
        e2 = fmaf(xv, r.z, e2);  e3 = fmaf(xv, r.w, e3);
    }

    float v0 = e0 + o0, v1 = e1 + o1, v2 = e2 + o2, v3 = e3 + o3;

    const unsigned FULL = 0xFFFFFFFFu;

    // Stage xor 1: even lanes keep comps {0,1}, odd lanes keep comps {2,3}.
    // Each lane sends the half its partner keeps.
    {
        bool hi = (t & 1);
        float s0 = hi ? v0 : v2;          // partner wants these
        float s1 = hi ? v1 : v3;
        float r0 = __shfl_xor_sync(FULL, s0, 1);
        float r1 = __shfl_xor_sync(FULL, s1, 1);
        float k0 = hi ? v2 : v0;          // the half this lane keeps
        float k1 = hi ? v3 : v1;
        v0 = k0 + r0;
        v1 = k1 + r1;
    }

    // Stage xor 2: keep one component. bit1==0 keeps v0, bit1==1 keeps v1.
    float w;
    {
        bool hi = (t & 2);
        float s = hi ? v0 : v1;           // send what partner keeps
        float r = __shfl_xor_sync(FULL, s, 2);
        float k = hi ? v1 : v0;
        w = k + r;
    }

    // Scalar butterfly over remaining lane bits.
    w += __shfl_xor_sync(FULL, w, 4);
    w += __shfl_xor_sync(FULL, w, 8);
    w += __shfl_xor_sync(FULL, w, 16);

    // Lane t (<4) holds component k = 2*(t&1) + ((t>>1)&1).
    if (t < 4) {
        int k = ((t & 1) << 1) | ((t >> 1) & 1);
        out[k] = w;
    }
}

extern "C" void kernel_launch(void* const* d_in, const int* in_sizes, int n_in,
                              void* d_out, int out_size) {
    const float* x        = (const float*)d_in[0];   // [1,4] float32
    const float* matrices = (const float*)d_in[1];   // [100,4,4] float32
    float* out            = (float*)d_out;           // [4] float32

    bigfanout_kernel<<<1, 32>>>(x, matrices, out);
}

// round 4
// speedup vs baseline: 1.5141x; 1.0141x over previous
#include <cuda_runtime.h>

// out[k] = sum_d x[d] * S[d][k],  S[d][k] = sum_n M[n][d][k].
// M flattened to 400 float4 rows (row p = (n,d), comps = k); lane t owns rows
// p = t + 32j, and since 32 % 4 == 0, d = t & 3 is fixed per lane.
//
// x is decoupled from the accumulation: the 13-row sum is pure FADDs, so the
// x load (L2 ~250cyc; L1 is flushed per launch on Blackwell) overlaps the
// whole add chain. xv is applied with one FMUL per component just before the
// lane-mixing stages (its first consumer).
//
// Reduction: 6 SHFLs, depth 5 (f32 REDUX is not supported by ptxas on sm_103):
//   stage xor 1: fold 4 comps -> 2   (2 parallel SHFLs)
//   stage xor 2: fold 2 comps -> 1   (1 SHFL)
//   stages xor 4,8,16: scalar butterfly (3 SHFLs)
// Lane t<4 stores out[k], k = 2*(t&1) + ((t>>1)&1).

__global__ void __launch_bounds__(32, 1)
bigfanout_kernel(const float* __restrict__ x,
                 const float* __restrict__ matrices,
                 float* __restrict__ out) {
    const int t = threadIdx.x;            // 0..31
    const float xv = x[t & 3];            // issued early; consumed late

    const float4* __restrict__ rows = reinterpret_cast<const float4*>(matrices);

    // Pure-add accumulation, dual accumulators to halve the FADD chain.
    float e0 = 0.f, e1 = 0.f, e2 = 0.f, e3 = 0.f;
    float o0 = 0.f, o1 = 0.f, o2 = 0.f, o3 = 0.f;

    #pragma unroll
    for (int j = 0; j < 12; j += 2) {
        float4 re = rows[t + 32 * j];
        float4 ro = rows[t + 32 * (j + 1)];
        e0 += re.x;  e1 += re.y;  e2 += re.z;  e3 += re.w;
        o0 += ro.x;  o1 += ro.y;  o2 += ro.z;  o3 += ro.w;
    }

    // Tail: rows 384..399, lanes 0..15. 384 % 4 == 0 so d = t&3 still holds.
    if (t < 16) {
        float4 r = rows[384 + t];
        e0 += r.x;  e1 += r.y;  e2 += r.z;  e3 += r.w;
    }

    // Apply x[d] once per component (first and only consumer of the x load).
    float v0 = (e0 + o0) * xv;
    float v1 = (e1 + o1) * xv;
    float v2 = (e2 + o2) * xv;
    float v3 = (e3 + o3) * xv;

    const unsigned FULL = 0xFFFFFFFFu;

    // Stage xor 1: even lanes keep comps {0,1}, odd lanes keep {2,3}.
    {
        bool hi = (t & 1);
        float s0 = hi ? v0 : v2;          // send what the partner keeps
        float s1 = hi ? v1 : v3;
        float r0 = __shfl_xor_sync(FULL, s0, 1);
        float r1 = __shfl_xor_sync(FULL, s1, 1);
        float k0 = hi ? v2 : v0;
        float k1 = hi ? v3 : v1;
        v0 = k0 + r0;
        v1 = k1 + r1;
    }

    // Stage xor 2: keep one component per lane.
    float w;
    {
        bool hi = (t & 2);
        float s = hi ? v0 : v1;
        float r = __shfl_xor_sync(FULL, s, 2);
        float k = hi ? v1 : v0;
        w = k + r;
    }

    // Scalar butterfly over remaining lane bits (8 lanes share t&3).
    w += __shfl_xor_sync(FULL, w, 4);
    w += __shfl_xor_sync(FULL, w, 8);
    w += __shfl_xor_sync(FULL, w, 16);

    // Lane t (<4) holds component k = 2*(t&1) + ((t>>1)&1).
    if (t < 4) {
        int k = ((t & 1) << 1) | ((t >> 1) & 1);
        out[k] = w;
    }
}

extern "C" void kernel_launch(void* const* d_in, const int* in_sizes, int n_in,
                              void* d_out, int out_size) {
    const float* x        = (const float*)d_in[0];   // [1,4] float32
    const float* matrices = (const float*)d_in[1];   // [100,4,4] float32
    float* out            = (float*)d_out;           // [4] float32

    bigfanout_kernel<<<1, 32>>>(x, matrices, out);
}